// round 10
// baseline (speedup 1.0000x reference)
#include <cuda_runtime.h>

#define NB 4
#define NC 200
#define NG 32
#define NN 32256
#define CH 128                    // anchors per block
#define NBX (NN / CH)             // 252
#define TOTAL_BLOCKS (NB * NBX)   // 1008 -> single wave
#define QPT ((CH * 50) / 256)     // 25 quads per thread in phase B
#define LOG2E 1.4426950408889634f
#define LN2   0.69314718055994531f

__device__ double g_acc[3];
__device__ unsigned g_cnt;
__device__ unsigned g_done;

__device__ __forceinline__ float f_ex2(float x){ float r; asm("ex2.approx.ftz.f32 %0,%1;" : "=f"(r) : "f"(x)); return r; }
__device__ __forceinline__ float f_lg2(float x){ float r; asm("lg2.approx.ftz.f32 %0,%1;" : "=f"(r) : "f"(x)); return r; }
__device__ __forceinline__ float f_rcp(float x){ float r; asm("rcp.approx.ftz.f32 %0,%1;" : "=f"(r) : "f"(x)); return r; }

// 2-MUFU core: ex2 + lg2 on MUFU; rcp via magic seed + 2 Newton (FMA pipe).
__device__ __forceinline__ float g0_2m(float x) {
    float t = x * LOG2E;
    float u = f_ex2(t);                    // MUFU
    float s = 1.f + u;
    float l = f_lg2(s);                    // MUFU
    float r = __int_as_float(0x7EF311C3 - __float_as_int(s));
    r = r * fmaf(-s, r, 2.f);
    r = r * fmaf(-s, r, 2.f);              // rel err ~6e-6
    float w = u * r;
    return l * w * w;
}

// 1-MUFU core: ex2 via deg-4 Estrin poly (shallow!), lg2 on MUFU, Newton rcp.
__device__ __forceinline__ float g0_1m(float x) {
    float y  = x * LOG2E;
    float tt = y + 12582912.f;                 // round-to-nearest int
    int   n  = __float_as_int(tt) - 0x4B400000;
    float fr = y - (tt - 12582912.f);          // fr in [-0.5, 0.5]
    // 2^fr, Taylor deg 4, Estrin (rel err ~4e-5)
    float fr2 = fr * fr;
    float e0  = fmaf(0.69314718f, fr, 1.f);
    float e1  = fmaf(0.055504109f, fr, 0.24022651f);
    float p   = fmaf(e1, fr2, e0);
    p = fmaf(0.0096181291f, fr2 * fr2, p);
    float u = __int_as_float(__float_as_int(p) + (int)((unsigned)n << 23));
    float s = 1.f + u;
    float l = f_lg2(s);                        // the only MUFU
    float r = __int_as_float(0x7EF311C3 - __float_as_int(s));
    r = r * fmaf(-s, r, 2.f);
    r = r * fmaf(-s, r, 2.f);
    float w = u * r;
    return l * w * w;
}

__global__ void __launch_bounds__(256, 7)
loss_fused(const float* __restrict__ logits,        // [B,N,C]
           const float* __restrict__ psegs,         // [B,N,3]
           const float* __restrict__ grids,         // [B,N]
           const float* __restrict__ fps,           // [B]
           const float* __restrict__ gts,           // [B,G,2]
           const int*   __restrict__ glab,          // [B,G]
           const unsigned char* __restrict__ mask,  // [B,N]
           float* __restrict__ out)                 // [3]
{
    __shared__ unsigned s_tgt[CH * 8];   // 224-bit class-target mask per anchor
    __shared__ float    s_gv[CH], s_p1[CH], s_p2[CH], s_vv[CH];
    __shared__ float    s_red[3 * 8];
    __shared__ int      s_redc[8];

    const int tid  = threadIdx.x;
    const int lane = tid & 31;
    const int warp = tid >> 5;
    const int b    = blockIdx.y;
    const int n0   = blockIdx.x * CH;

    #pragma unroll
    for (int k = 0; k < 4; ++k) s_tgt[tid + k * 256] = 0u;
    if (tid < CH) {
        long long bn = (long long)b * NN + n0 + tid;
        s_gv[tid] = grids[bn];
        s_p1[tid] = psegs[bn * 3 + 1];
        s_p2[tid] = psegs[bn * 3 + 2];
        s_vv[tid] = mask[bn] ? 0.f : 1.f;
    }
    __syncthreads();

    // ---------------- Phase A: matching + seg/IoU + target masks ----------
    float2 seg  = ((const float2*)gts)[b * NG + lane];
    float s_g   = seg.x, e_g = seg.y;
    float len_g = e_g - s_g;
    int   lbl   = glab[b * NG + lane];
    float Cm    = 3.0f * fps[b] * 1.41421356237309515f;  // 3*fps*sqrt(2)

    int lvl = (n0 >= 16384) + (n0 >= 24576) + (n0 >= 28672) + (n0 >= 30720) + (n0 >= 31744);
    float lo = (lvl == 0) ? 0.f : Cm * (float)(1 << (lvl - 1));
    float hi = (lvl == 5) ? __int_as_float(0x7f800000) : Cm * (float)(1 << lvl);
    bool inb = (len_g >= lo) && (len_g < hi);

    float ce_acc = 0.f, seg_acc = 0.f, iou_acc = 0.f;
    int cnt = 0;

    #pragma unroll 4
    for (int i = 0; i < CH / 8; ++i) {   // 16 anchors per warp
        int a = warp * (CH / 8) + i;
        float gv = s_gv[a];
        bool pos = inb && (gv > s_g) && (gv < e_g);
        if (pos) {
            cnt++;
            float ps1 = s_p1[a], ps2 = s_p2[a];
            float d1 = ps1 - __logf(gv - s_g);
            float d2 = ps2 - __logf(e_g - gv);
            float a1 = fabsf(d1), a2 = fabsf(d2);
            seg_acc += (a1 < 1.f ? 0.5f * d1 * d1 : a1 - 0.5f)
                     + (a2 < 1.f ? 0.5f * d2 * d2 : a2 - 0.5f);
            float pls = gv - __expf(ps1);
            float ple = gv + __expf(ps2);
            float inter = fmaxf(fminf(ple, e_g) - fmaxf(pls, s_g), 0.f);
            float uni   = (ple - pls) + len_g - inter;
            iou_acc += 1.f - __fdividef(inter, uni);
            atomicOr(&s_tgt[a * 8 + (lbl >> 5)], 1u << (lbl & 31));
        }
    }
    // no barrier: phase B reads no phase-A shared state

    // ---------------- Phase B: 1.5-MUFU/elem focal stream ------------------
    // x,z -> 2-MUFU path; y,w -> 1-MUFU (ex2-poly) path. Balances MUFU vs FMA.
    const float4* basep = (const float4*)(logits + ((size_t)b * NN + n0) * NC);
    float c0 = 0.f, c1 = 0.f, c2 = 0.f, c3 = 0.f;
    #pragma unroll
    for (int k = 0; k < QPT; ++k) {
        float4 v = basep[tid + k * 256];
        c0 += g0_2m(v.x);
        c1 += g0_1m(v.y);
        c2 += g0_2m(v.z);
        c3 += g0_1m(v.w);
    }
    ce_acc += (c0 + c1) + (c2 + c3);
    __syncthreads();   // s_tgt / s_vv complete before phase C

    // ---------------- Phase C: corrections ---------------------------------
    const float* rowbase = logits + ((size_t)b * NN + n0) * NC;

    // (1) invalid anchors: subtract whole-row t=0 contribution (rare path).
    for (int a = warp; a < CH; a += 8) {
        if (s_vv[a] == 0.f) {
            const float* rp = rowbase + a * NC;
            float sub = 0.f;
            for (int c = lane; c < NC; c += 32) sub += g0_2m(rp[c]);
            #pragma unroll
            for (int o = 16; o; o >>= 1) sub += __shfl_xor_sync(0xffffffffu, sub, o);
            if (lane == 0) ce_acc -= sub;
        }
    }

    // (2) sparse t=1 cells: add (fl1 - fl0) in lg2 units:
    //     (1/3)*(l - x*log2e)*r^2 - l*w^2   (times valid)
    #pragma unroll
    for (int kk = 0; kk < 4; ++kk) {
        int wq = tid + kk * 256;
        unsigned m = s_tgt[wq];
        if (m) {
            int a  = wq >> 3;
            int wi = wq & 7;
            float vf = s_vv[a];
            const float* rp = rowbase + a * NC + wi * 32;
            do {
                int bp = __ffs(m) - 1; m &= m - 1;
                float x = rp[bp];
                float t = x * LOG2E;
                float u = f_ex2(t);
                float s = 1.f + u;
                float r = f_rcp(s);
                float l = f_lg2(s);
                float w = u * r;
                ce_acc += vf * (0.33333333333f * (l - t) * r * r - l * w * w);
            } while (m);
        }
    }

    // ---------------- Reduction + last-block finalize ----------------------
    #pragma unroll
    for (int o = 16; o; o >>= 1) {
        ce_acc  += __shfl_xor_sync(0xffffffffu, ce_acc,  o);
        seg_acc += __shfl_xor_sync(0xffffffffu, seg_acc, o);
        iou_acc += __shfl_xor_sync(0xffffffffu, iou_acc, o);
        cnt     += __shfl_xor_sync(0xffffffffu, cnt,     o);
    }
    if (lane == 0) {
        s_red[warp]      = ce_acc;
        s_red[8 + warp]  = seg_acc;
        s_red[16 + warp] = iou_acc;
        s_redc[warp]     = cnt;
    }
    __syncthreads();
    if (tid == 0) {
        double ce = 0.0, sg = 0.0, io = 0.0; int c = 0;
        #pragma unroll
        for (int w = 0; w < 8; ++w) {
            ce += (double)s_red[w];
            sg += (double)s_red[8 + w];
            io += (double)s_red[16 + w];
            c  += s_redc[w];
        }
        atomicAdd(&g_acc[0], ce);
        atomicAdd(&g_acc[1], sg);
        atomicAdd(&g_acc[2], io);
        atomicAdd(&g_cnt, (unsigned)c);
        __threadfence();
        unsigned t = atomicAdd(&g_done, 1u);
        if (t == TOTAL_BLOCKS - 1) {
            double np = (double)atomicAdd(&g_cnt, 0u);
            if (np < 1.0) np = 1.0;
            double a0 = atomicAdd(&g_acc[0], 0.0);
            double a1 = atomicAdd(&g_acc[1], 0.0);
            double a2 = atomicAdd(&g_acc[2], 0.0);
            out[0] = (float)(a0 * (0.75 * (double)LN2) / np);  // deferred 0.75*ln2
            out[1] = (float)(a1 / np);
            out[2] = (float)(a2 / np);
            g_acc[0] = 0.0; g_acc[1] = 0.0; g_acc[2] = 0.0;
            g_cnt = 0u; g_done = 0u;
        }
    }
}

extern "C" void kernel_launch(void* const* d_in, const int* in_sizes, int n_in,
                              void* d_out, int out_size) {
    const float*         logits = (const float*)d_in[0];
    const float*         psegs  = (const float*)d_in[1];
    const float*         grids  = (const float*)d_in[2];
    const float*         fps    = (const float*)d_in[3];
    const float*         gts    = (const float*)d_in[4];
    const int*           glab   = (const int*)d_in[5];
    const unsigned char* maskp  = (const unsigned char*)d_in[6];
    float* out = (float*)d_out;

    dim3 grid(NBX, NB);
    loss_fused<<<grid, 256>>>(logits, psegs, grids, fps, gts, glab, maskp, out);
    (void)in_sizes; (void)n_in; (void)out_size;
}

// round 13
// speedup vs baseline: 1.1903x; 1.1903x over previous
#include <cuda_runtime.h>

#define NB 4
#define NC 200
#define NG 32
#define NN 32256
#define CH 128                    // anchors per block
#define NBX (NN / CH)             // 252
#define TOTAL_BLOCKS (NB * NBX)   // 1008 -> single wave
#define QPT ((CH * 50) / 256)     // 25 quads per thread in phase B
#define LOG2E 1.4426950408889634f
#define LN2   0.69314718055994531f

__device__ double g_acc[3];
__device__ unsigned g_cnt;
__device__ unsigned g_done;

__device__ __forceinline__ float f_ex2(float x){ float r; asm("ex2.approx.ftz.f32 %0,%1;" : "=f"(r) : "f"(x)); return r; }
__device__ __forceinline__ float f_lg2(float x){ float r; asm("lg2.approx.ftz.f32 %0,%1;" : "=f"(r) : "f"(x)); return r; }
__device__ __forceinline__ float f_rcp(float x){ float r; asm("rcp.approx.ftz.f32 %0,%1;" : "=f"(r) : "f"(x)); return r; }

// 2-MUFU focal core: lg2(1+e^x) * sigmoid(x)^2.
// ex2 + lg2 on MUFU; reciprocal via magic seed + one Halley step (3 FMA,
// cubic convergence: |rel err| <= (0.034)^3 ~ 4e-5, sign-alternating).
__device__ __forceinline__ float g0_2m(float x) {
    float t = x * LOG2E;
    float u = f_ex2(t);                    // MUFU #1
    float s = 1.f + u;
    float l = f_lg2(s);                    // MUFU #2
    float r0 = __int_as_float(0x7EF311C3 - __float_as_int(s));
    float h  = fmaf(-s, r0, 1.f);          // h = 1 - s*r0
    float hh = fmaf(h, h, h);              // h + h^2
    float r  = fmaf(r0, hh, r0);           // r0*(1 + h + h^2)
    float w = u * r;                       // sigmoid(x)
    return l * w * w;
}

__global__ void __launch_bounds__(256, 7)
loss_fused(const float* __restrict__ logits,        // [B,N,C]
           const float* __restrict__ psegs,         // [B,N,3]
           const float* __restrict__ grids,         // [B,N]
           const float* __restrict__ fps,           // [B]
           const float* __restrict__ gts,           // [B,G,2]
           const int*   __restrict__ glab,          // [B,G]
           const unsigned char* __restrict__ mask,  // [B,N]
           float* __restrict__ out)                 // [3]
{
    __shared__ unsigned s_tgt[CH * 8];   // 224-bit class-target mask per anchor
    __shared__ float    s_gv[CH], s_p1[CH], s_p2[CH], s_vv[CH];
    __shared__ float    s_red[3 * 8];
    __shared__ int      s_redc[8];

    const int tid  = threadIdx.x;
    const int lane = tid & 31;
    const int warp = tid >> 5;
    const int b    = blockIdx.y;
    const int n0   = blockIdx.x * CH;

    #pragma unroll
    for (int k = 0; k < 4; ++k) s_tgt[tid + k * 256] = 0u;
    if (tid < CH) {
        long long bn = (long long)b * NN + n0 + tid;
        s_gv[tid] = grids[bn];
        s_p1[tid] = psegs[bn * 3 + 1];
        s_p2[tid] = psegs[bn * 3 + 2];
        s_vv[tid] = mask[bn] ? 0.f : 1.f;
    }
    __syncthreads();

    // ---------------- Phase A: matching + seg/IoU + target masks ----------
    float2 seg  = ((const float2*)gts)[b * NG + lane];
    float s_g   = seg.x, e_g = seg.y;
    float len_g = e_g - s_g;
    int   lbl   = glab[b * NG + lane];
    float Cm    = 3.0f * fps[b] * 1.41421356237309515f;  // 3*fps*sqrt(2)

    int lvl = (n0 >= 16384) + (n0 >= 24576) + (n0 >= 28672) + (n0 >= 30720) + (n0 >= 31744);
    float lo = (lvl == 0) ? 0.f : Cm * (float)(1 << (lvl - 1));
    float hi = (lvl == 5) ? __int_as_float(0x7f800000) : Cm * (float)(1 << lvl);
    bool inb = (len_g >= lo) && (len_g < hi);

    float ce_acc = 0.f, seg_acc = 0.f, iou_acc = 0.f;
    int cnt = 0;

    #pragma unroll 4
    for (int i = 0; i < CH / 8; ++i) {   // 16 anchors per warp
        int a = warp * (CH / 8) + i;
        float gv = s_gv[a];
        bool pos = inb && (gv > s_g) && (gv < e_g);
        if (pos) {
            cnt++;
            float ps1 = s_p1[a], ps2 = s_p2[a];
            float d1 = ps1 - __logf(gv - s_g);
            float d2 = ps2 - __logf(e_g - gv);
            float a1 = fabsf(d1), a2 = fabsf(d2);
            seg_acc += (a1 < 1.f ? 0.5f * d1 * d1 : a1 - 0.5f)
                     + (a2 < 1.f ? 0.5f * d2 * d2 : a2 - 0.5f);
            float pls = gv - __expf(ps1);
            float ple = gv + __expf(ps2);
            float inter = fmaxf(fminf(ple, e_g) - fmaxf(pls, s_g), 0.f);
            float uni   = (ple - pls) + len_g - inter;
            iou_acc += 1.f - __fdividef(inter, uni);
            atomicOr(&s_tgt[a * 8 + (lbl >> 5)], 1u << (lbl & 31));
        }
    }
    // no barrier: phase B reads no phase-A shared state

    // ---------------- Phase B: homogeneous 2-MUFU focal stream -------------
    // Manual double-buffer: iteration k+1's load issues before k's math, so
    // every LDG has ~50 warp-instructions of latency cover.
    const float4* basep = (const float4*)(logits + ((size_t)b * NN + n0) * NC);
    float c0 = 0.f, c1 = 0.f, c2 = 0.f, c3 = 0.f;
    float4 v = basep[tid];
    #pragma unroll
    for (int k = 0; k < QPT; ++k) {
        float4 vn;
        if (k + 1 < QPT) vn = basep[tid + (k + 1) * 256];
        c0 += g0_2m(v.x);
        c1 += g0_2m(v.y);
        c2 += g0_2m(v.z);
        c3 += g0_2m(v.w);
        if (k + 1 < QPT) v = vn;
    }
    ce_acc += (c0 + c1) + (c2 + c3);
    __syncthreads();   // s_tgt / s_vv complete before phase C

    // ---------------- Phase C: corrections ---------------------------------
    const float* rowbase = logits + ((size_t)b * NN + n0) * NC;

    // (1) invalid anchors: subtract whole-row t=0 contribution (rare path).
    for (int a = warp; a < CH; a += 8) {
        if (s_vv[a] == 0.f) {
            const float* rp = rowbase + a * NC;
            float sub = 0.f;
            for (int c = lane; c < NC; c += 32) sub += g0_2m(rp[c]);
            #pragma unroll
            for (int o = 16; o; o >>= 1) sub += __shfl_xor_sync(0xffffffffu, sub, o);
            if (lane == 0) ce_acc -= sub;
        }
    }

    // (2) sparse t=1 cells: add (fl1 - fl0) in lg2 units:
    //     (1/3)*(l - x*log2e)*r^2 - l*w^2   (times valid)
    #pragma unroll
    for (int kk = 0; kk < 4; ++kk) {
        int wq = tid + kk * 256;
        unsigned m = s_tgt[wq];
        if (m) {
            int a  = wq >> 3;
            int wi = wq & 7;
            float vf = s_vv[a];
            const float* rp = rowbase + a * NC + wi * 32;
            do {
                int bp = __ffs(m) - 1; m &= m - 1;
                float x = rp[bp];
                float t = x * LOG2E;
                float u = f_ex2(t);
                float s = 1.f + u;
                float r = f_rcp(s);
                float l = f_lg2(s);
                float w = u * r;
                ce_acc += vf * (0.33333333333f * (l - t) * r * r - l * w * w);
            } while (m);
        }
    }

    // ---------------- Reduction + last-block finalize ----------------------
    #pragma unroll
    for (int o = 16; o; o >>= 1) {
        ce_acc  += __shfl_xor_sync(0xffffffffu, ce_acc,  o);
        seg_acc += __shfl_xor_sync(0xffffffffu, seg_acc, o);
        iou_acc += __shfl_xor_sync(0xffffffffu, iou_acc, o);
        cnt     += __shfl_xor_sync(0xffffffffu, cnt,     o);
    }
    if (lane == 0) {
        s_red[warp]      = ce_acc;
        s_red[8 + warp]  = seg_acc;
        s_red[16 + warp] = iou_acc;
        s_redc[warp]     = cnt;
    }
    __syncthreads();
    if (tid == 0) {
        double ce = 0.0, sg = 0.0, io = 0.0; int c = 0;
        #pragma unroll
        for (int w = 0; w < 8; ++w) {
            ce += (double)s_red[w];
            sg += (double)s_red[8 + w];
            io += (double)s_red[16 + w];
            c  += s_redc[w];
        }
        atomicAdd(&g_acc[0], ce);
        atomicAdd(&g_acc[1], sg);
        atomicAdd(&g_acc[2], io);
        atomicAdd(&g_cnt, (unsigned)c);
        __threadfence();
        unsigned t = atomicAdd(&g_done, 1u);
        if (t == TOTAL_BLOCKS - 1) {
            double np = (double)atomicAdd(&g_cnt, 0u);
            if (np < 1.0) np = 1.0;
            double a0 = atomicAdd(&g_acc[0], 0.0);
            double a1 = atomicAdd(&g_acc[1], 0.0);
            double a2 = atomicAdd(&g_acc[2], 0.0);
            out[0] = (float)(a0 * (0.75 * (double)LN2) / np);  // deferred 0.75*ln2
            out[1] = (float)(a1 / np);
            out[2] = (float)(a2 / np);
            g_acc[0] = 0.0; g_acc[1] = 0.0; g_acc[2] = 0.0;
            g_cnt = 0u; g_done = 0u;
        }
    }
}

extern "C" void kernel_launch(void* const* d_in, const int* in_sizes, int n_in,
                              void* d_out, int out_size) {
    const float*         logits = (const float*)d_in[0];
    const float*         psegs  = (const float*)d_in[1];
    const float*         grids  = (const float*)d_in[2];
    const float*         fps    = (const float*)d_in[3];
    const float*         gts    = (const float*)d_in[4];
    const int*           glab   = (const int*)d_in[5];
    const unsigned char* maskp  = (const unsigned char*)d_in[6];
    float* out = (float*)d_out;

    dim3 grid(NBX, NB);
    loss_fused<<<grid, 256>>>(logits, psegs, grids, fps, gts, glab, maskp, out);
    (void)in_sizes; (void)n_in; (void)out_size;
}

// round 14
// speedup vs baseline: 1.2031x; 1.0107x over previous
#include <cuda_runtime.h>

#define NB 4
#define NC 200
#define NG 32
#define NN 32256
#define CH 128                    // anchors per block
#define NBX (NN / CH)             // 252
#define TOTAL_BLOCKS (NB * NBX)   // 1008 -> single wave
#define QPT ((CH * 50) / 256)     // 25 quads per thread in phase B
#define LOG2E 1.4426950408889634f
#define LN2   0.69314718055994531f

__device__ double g_acc[3];
__device__ unsigned g_cnt;
__device__ unsigned g_done;

__device__ __forceinline__ float f_ex2(float x){ float r; asm("ex2.approx.ftz.f32 %0,%1;" : "=f"(r) : "f"(x)); return r; }
__device__ __forceinline__ float f_lg2(float x){ float r; asm("lg2.approx.ftz.f32 %0,%1;" : "=f"(r) : "f"(x)); return r; }
__device__ __forceinline__ float f_rcp(float x){ float r; asm("rcp.approx.ftz.f32 %0,%1;" : "=f"(r) : "f"(x)); return r; }

// f32 2-MUFU core (phase C rare paths)
__device__ __forceinline__ float g0_2m(float x) {
    float t = x * LOG2E;
    float u = f_ex2(t);
    float s = 1.f + u;
    float l = f_lg2(s);
    float r0 = __int_as_float(0x7EF311C3 - __float_as_int(s));
    float h  = fmaf(-s, r0, 1.f);
    float r  = fmaf(r0, fmaf(h, h, h), r0);
    float w = u * r;
    return l * w * w;
}

// Paired focal: processes TWO elements with 3 MUFU total (1.5/elem):
//   - ex2.approx.f16x2: both exponentials in ONE MUFU op
//   - lg2.approx.f32 per element
//   - both reciprocals from ONE magic-seed+Halley on the product s0*s1
__device__ __forceinline__ void g0_pair(float x0, float x1, float& acc0, float& acc1) {
    float t0 = x0 * LOG2E, t1 = x1 * LOG2E;
    unsigned hp, up;
    asm("cvt.rn.f16x2.f32 %0, %1, %2;" : "=r"(hp) : "f"(t1), "f"(t0));  // lo=t0, hi=t1
    asm("ex2.approx.f16x2 %0, %1;" : "=r"(up) : "r"(hp));               // MUFU (dual)
    float u0, u1;
    asm("{.reg .f16 lo, hi; mov.b32 {lo, hi}, %2; cvt.f32.f16 %0, lo; cvt.f32.f16 %1, hi;}"
        : "=f"(u0), "=f"(u1) : "r"(up));
    float s0 = 1.f + u0, s1 = 1.f + u1;
    float l0 = f_lg2(s0);                  // MUFU
    float l1 = f_lg2(s1);                  // MUFU
    float p  = s0 * s1;
    float rp0 = __int_as_float(0x7EF311C3 - __float_as_int(p));
    float h  = fmaf(-p, rp0, 1.f);
    float rp = fmaf(rp0, fmaf(h, h, h), rp0);   // 1/(s0*s1), rel ~4e-5
    float w0 = u0 * (rp * s1);             // u0/s0
    float w1 = u1 * (rp * s0);             // u1/s1
    acc0 = fmaf(l0, w0 * w0, acc0);
    acc1 = fmaf(l1, w1 * w1, acc1);
}

__global__ void __launch_bounds__(256, 7)
loss_fused(const float* __restrict__ logits,        // [B,N,C]
           const float* __restrict__ psegs,         // [B,N,3]
           const float* __restrict__ grids,         // [B,N]
           const float* __restrict__ fps,           // [B]
           const float* __restrict__ gts,           // [B,G,2]
           const int*   __restrict__ glab,          // [B,G]
           const unsigned char* __restrict__ mask,  // [B,N]
           float* __restrict__ out)                 // [3]
{
    __shared__ unsigned s_tgt[CH * 8];   // 224-bit class-target mask per anchor
    __shared__ float    s_gv[CH], s_p1[CH], s_p2[CH], s_vv[CH];
    __shared__ float    s_red[3 * 8];
    __shared__ int      s_redc[8];

    const int tid  = threadIdx.x;
    const int lane = tid & 31;
    const int warp = tid >> 5;
    const int b    = blockIdx.y;
    const int n0   = blockIdx.x * CH;

    #pragma unroll
    for (int k = 0; k < 4; ++k) s_tgt[tid + k * 256] = 0u;
    if (tid < CH) {
        long long bn = (long long)b * NN + n0 + tid;
        s_gv[tid] = grids[bn];
        s_p1[tid] = psegs[bn * 3 + 1];
        s_p2[tid] = psegs[bn * 3 + 2];
        s_vv[tid] = mask[bn] ? 0.f : 1.f;
    }
    __syncthreads();

    // ---------------- Phase A: matching + seg/IoU + target masks ----------
    float2 seg  = ((const float2*)gts)[b * NG + lane];
    float s_g   = seg.x, e_g = seg.y;
    float len_g = e_g - s_g;
    int   lbl   = glab[b * NG + lane];
    float Cm    = 3.0f * fps[b] * 1.41421356237309515f;  // 3*fps*sqrt(2)

    int lvl = (n0 >= 16384) + (n0 >= 24576) + (n0 >= 28672) + (n0 >= 30720) + (n0 >= 31744);
    float lo = (lvl == 0) ? 0.f : Cm * (float)(1 << (lvl - 1));
    float hi = (lvl == 5) ? __int_as_float(0x7f800000) : Cm * (float)(1 << lvl);
    bool inb = (len_g >= lo) && (len_g < hi);

    float ce_acc = 0.f, seg_acc = 0.f, iou_acc = 0.f;
    int cnt = 0;

    #pragma unroll 4
    for (int i = 0; i < CH / 8; ++i) {   // 16 anchors per warp
        int a = warp * (CH / 8) + i;
        float gv = s_gv[a];
        bool pos = inb && (gv > s_g) && (gv < e_g);
        if (pos) {
            cnt++;
            float ps1 = s_p1[a], ps2 = s_p2[a];
            float d1 = ps1 - __logf(gv - s_g);
            float d2 = ps2 - __logf(e_g - gv);
            float a1 = fabsf(d1), a2 = fabsf(d2);
            seg_acc += (a1 < 1.f ? 0.5f * d1 * d1 : a1 - 0.5f)
                     + (a2 < 1.f ? 0.5f * d2 * d2 : a2 - 0.5f);
            float pls = gv - __expf(ps1);
            float ple = gv + __expf(ps2);
            float inter = fmaxf(fminf(ple, e_g) - fmaxf(pls, s_g), 0.f);
            float uni   = (ple - pls) + len_g - inter;
            iou_acc += 1.f - __fdividef(inter, uni);
            atomicOr(&s_tgt[a * 8 + (lbl >> 5)], 1u << (lbl & 31));
        }
    }
    // no barrier: phase B reads no phase-A shared state

    // ---------------- Phase B: 1.5-MUFU/elem focal stream (f16x2 ex2) ------
    // Double-buffer prefetch: next iteration's load issues before this math.
    const float4* basep = (const float4*)(logits + ((size_t)b * NN + n0) * NC);
    float c0 = 0.f, c1 = 0.f, c2 = 0.f, c3 = 0.f;
    float4 v = basep[tid];
    #pragma unroll
    for (int k = 0; k < QPT; ++k) {
        float4 vn;
        if (k + 1 < QPT) vn = basep[tid + (k + 1) * 256];
        g0_pair(v.x, v.y, c0, c1);
        g0_pair(v.z, v.w, c2, c3);
        if (k + 1 < QPT) v = vn;
    }
    ce_acc += (c0 + c1) + (c2 + c3);
    __syncthreads();   // s_tgt / s_vv complete before phase C

    // ---------------- Phase C: corrections ---------------------------------
    const float* rowbase = logits + ((size_t)b * NN + n0) * NC;

    // (1) invalid anchors: subtract whole-row t=0 contribution (rare path).
    //     Must match phase B numerics -> use the same paired evaluator.
    for (int a = warp; a < CH; a += 8) {
        if (s_vv[a] == 0.f) {
            const float* rp = rowbase + a * NC;
            float sA = 0.f, sB = 0.f;
            for (int c = lane * 2; c < NC; c += 64)
                g0_pair(rp[c], rp[c + 1], sA, sB);
            float sub = sA + sB;
            #pragma unroll
            for (int o = 16; o; o >>= 1) sub += __shfl_xor_sync(0xffffffffu, sub, o);
            if (lane == 0) ce_acc -= sub;
        }
    }

    // (2) sparse t=1 cells: remove the f16-path fl0 and add exact-ish fl1:
    //     delta = (1/3)*(l - t)*r^2 - l_f16path*w_f16path^2
    //     (evaluate the subtracted term with the SAME paired core numerics)
    #pragma unroll
    for (int kk = 0; kk < 4; ++kk) {
        int wq = tid + kk * 256;
        unsigned m = s_tgt[wq];
        if (m) {
            int a  = wq >> 3;
            int wi = wq & 7;
            float vf = s_vv[a];
            const float* rp = rowbase + a * NC + wi * 32;
            do {
                int bp = __ffs(m) - 1; m &= m - 1;
                float x = rp[bp];
                // exact-ish fl1 (f32 MUFU path)
                float t = x * LOG2E;
                float u = f_ex2(t);
                float s = 1.f + u;
                float r = f_rcp(s);
                float l = f_lg2(s);
                // subtract the same value phase B added for this cell
                float dummy = 0.f, fb = 0.f;
                g0_pair(x, x, fb, dummy);
                ce_acc += vf * (0.33333333333f * (l - t) * r * r - fb);
            } while (m);
        }
    }

    // ---------------- Reduction + last-block finalize ----------------------
    #pragma unroll
    for (int o = 16; o; o >>= 1) {
        ce_acc  += __shfl_xor_sync(0xffffffffu, ce_acc,  o);
        seg_acc += __shfl_xor_sync(0xffffffffu, seg_acc, o);
        iou_acc += __shfl_xor_sync(0xffffffffu, iou_acc, o);
        cnt     += __shfl_xor_sync(0xffffffffu, cnt,     o);
    }
    if (lane == 0) {
        s_red[warp]      = ce_acc;
        s_red[8 + warp]  = seg_acc;
        s_red[16 + warp] = iou_acc;
        s_redc[warp]     = cnt;
    }
    __syncthreads();
    if (tid == 0) {
        double ce = 0.0, sg = 0.0, io = 0.0; int c = 0;
        #pragma unroll
        for (int w = 0; w < 8; ++w) {
            ce += (double)s_red[w];
            sg += (double)s_red[8 + w];
            io += (double)s_red[16 + w];
            c  += s_redc[w];
        }
        atomicAdd(&g_acc[0], ce);
        atomicAdd(&g_acc[1], sg);
        atomicAdd(&g_acc[2], io);
        atomicAdd(&g_cnt, (unsigned)c);
        __threadfence();
        unsigned t = atomicAdd(&g_done, 1u);
        if (t == TOTAL_BLOCKS - 1) {
            double np = (double)atomicAdd(&g_cnt, 0u);
            if (np < 1.0) np = 1.0;
            double a0 = atomicAdd(&g_acc[0], 0.0);
            double a1 = atomicAdd(&g_acc[1], 0.0);
            double a2 = atomicAdd(&g_acc[2], 0.0);
            out[0] = (float)(a0 * (0.75 * (double)LN2) / np);  // deferred 0.75*ln2
            out[1] = (float)(a1 / np);
            out[2] = (float)(a2 / np);
            g_acc[0] = 0.0; g_acc[1] = 0.0; g_acc[2] = 0.0;
            g_cnt = 0u; g_done = 0u;
        }
    }
}

extern "C" void kernel_launch(void* const* d_in, const int* in_sizes, int n_in,
                              void* d_out, int out_size) {
    const float*         logits = (const float*)d_in[0];
    const float*         psegs  = (const float*)d_in[1];
    const float*         grids  = (const float*)d_in[2];
    const float*         fps    = (const float*)d_in[3];
    const float*         gts    = (const float*)d_in[4];
    const int*           glab   = (const int*)d_in[5];
    const unsigned char* maskp  = (const unsigned char*)d_in[6];
    float* out = (float*)d_out;

    dim3 grid(NBX, NB);
    loss_fused<<<grid, 256>>>(logits, psegs, grids, fps, gts, glab, maskp, out);
    (void)in_sizes; (void)n_in; (void)out_size;
}